// round 10
// baseline (speedup 1.0000x reference)
#include <cuda_runtime.h>
#include <cuda_bf16.h>
#include <math.h>
#include <stdint.h>

// ---------------- constants ----------------
#define BB 16
#define CC 256
#define HH 64
#define WW 64
#define NN 4096            // tokens per batch
#define BN (BB*NN)         // 65536 total tokens
#define CRD 128
#define NHD 8
#define NRD 16             // reduced tokens (4x4)
#define HID 1024
#define HALF 512

typedef __nv_bfloat16 bf16;

// ---------------- scratch (device globals; no allocation) ----------------
__device__ float g_xh[BB*CC*HH];
__device__ float g_xw[BB*CC*WW];
__device__ float g_res[(size_t)BN*CC];      // gated tokens (fp32 residual)
__device__ bf16  g_tln[(size_t)BN*CC];      // LN1/LN2 out (bf16, GEMM A)
__device__ float g_q[(size_t)BN*CRD];
__device__ bf16  g_o[(size_t)BN*CC];        // attention out (bf16, GEMM A)
__device__ float g_red[BB*CC*NRD];
__device__ float g_k[BB*NRD*CRD];
__device__ float g_v[BB*NRD*CC];
__device__ bf16  g_h[(size_t)BN*HID];       // fc1 out (bf16); tail reused as fc2 fp32 temp
__device__ bf16  g_x2t[(size_t)BN*HALF];    // gnormed x2, token layout
__device__ bf16  g_x2i[(size_t)BN*HALF];    // image layout
__device__ bf16  g_x2c[(size_t)BN*HALF];    // after gconv, image layout
__device__ bf16  g_gate[(size_t)BN*HALF];   // x1*x2 token layout (GEMM A)
// transposed bf16 weights [N,K]
__device__ bf16 g_qT[CRD*CC];
__device__ bf16 g_projT[CC*CC];
__device__ bf16 g_fc1T[HID*CC];
__device__ bf16 g_fc2T[CC*HALF];

__device__ __forceinline__ float gelu_f(float v){
    return 0.5f * v * (1.0f + erff(v * 0.70710678118654752f));
}
__device__ __forceinline__ uint32_t smem_u32(const void* p){
    uint32_t a;
    asm("{ .reg .u64 t; cvta.to.shared.u64 t, %1; cvt.u32.u64 %0, t; }" : "=r"(a) : "l"(p));
    return a;
}
__device__ __forceinline__ void cp16(uint32_t dst, const void* src){
    asm volatile("cp.async.cg.shared.global [%0], [%1], 16;" :: "r"(dst), "l"(src));
}
#define CP_COMMIT() asm volatile("cp.async.commit_group;" ::: "memory")
#define CP_WAIT0()  asm volatile("cp.async.wait_group 0;" ::: "memory")
#define CP_WAIT1()  asm volatile("cp.async.wait_group 1;" ::: "memory")

__device__ __forceinline__ void mma_bf16(float* c, const uint32_t* a, const uint32_t* b){
    asm volatile(
        "mma.sync.aligned.m16n8k16.row.col.f32.bf16.bf16.f32 "
        "{%0,%1,%2,%3}, {%4,%5,%6,%7}, {%8,%9}, {%0,%1,%2,%3};"
        : "+f"(c[0]), "+f"(c[1]), "+f"(c[2]), "+f"(c[3])
        : "r"(a[0]), "r"(a[1]), "r"(a[2]), "r"(a[3]), "r"(b[0]), "r"(b[1]));
}

// ---------------- weight transpose to bf16: WT[n*K+k] = bf16(W[k*N+n]) ----------------
__global__ void k_tr(const float* __restrict__ W, bf16* __restrict__ WT, int K, int Nn){
    __shared__ float t[32][33];
    int k0 = blockIdx.y*32, n0 = blockIdx.x*32;
    int tx = threadIdx.x, ty = threadIdx.y;
    for (int r = ty; r < 32; r += 8)
        t[r][tx] = W[(size_t)(k0+r)*Nn + n0 + tx];
    __syncthreads();
    for (int r = ty; r < 32; r += 8)
        WT[(size_t)(n0+r)*K + k0 + tx] = __float2bfloat16(t[tx][r]);
}

// ---------------- bf16 mma.sync GEMM: C[M,N] = A[M,K] * WT[N,K]^T ----------------
// CTA 128 x NT (NT=128 or 256), warp tile 64 x NT/4, K chunk 32 bf16, cp.async double buffer.
// smem pitch 40 bf16 (80B) -> conflict-free 32-bit fragment loads.
#define PITCH 40
template<int NT, bool GELU, bool RESID, bool OUTBF16>
__global__ __launch_bounds__(256) void k_gemm_bf(
        const bf16* __restrict__ A, const bf16* __restrict__ WT,
        const float* __restrict__ bias, const float* __restrict__ resid,
        void* __restrict__ Cc, int M, int Nn, int K){
    extern __shared__ bf16 sm[];
    // layout (bf16 units): A0=0, A1=5120, B0=10240, B1=10240+NT*40
    uint32_t sbase = smem_u32(sm);
    int tid = threadIdx.x, wid = tid >> 5, lane = tid & 31;
    int m0 = blockIdx.y * 128, n0 = blockIdx.x * NT;
    int wm = (wid & 1) * 64;
    int wn = (wid >> 1) * (NT/4);
    const int NFRAG = NT/32;

    float acc[4][NFRAG][4];
    #pragma unroll
    for (int i = 0; i < 4; i++)
        #pragma unroll
        for (int j = 0; j < NFRAG; j++)
            #pragma unroll
            for (int q = 0; q < 4; q++) acc[i][j][q] = 0.f;

    int NC = K >> 5;
    int prow = tid >> 2, psg = tid & 3;    // 64 rows per 256-thread pass, 4 segs

    // prefetch chunk 0
    {
        const bf16* Ag = A + (size_t)m0*K;
        #pragma unroll
        for (int i = 0; i < 2; i++){
            int row = prow + i*64;
            cp16(sbase + (uint32_t)(row*PITCH + psg*8)*2, Ag + (size_t)row*K + psg*8);
        }
        const bf16* Bg = WT + (size_t)n0*K;
        #pragma unroll
        for (int i = 0; i < NT/64; i++){
            int row = prow + i*64;
            cp16(sbase + (uint32_t)(10240 + row*PITCH + psg*8)*2, Bg + (size_t)row*K + psg*8);
        }
        CP_COMMIT();
    }

    for (int ch = 0; ch < NC; ch++){
        int buf = ch & 1;
        if (ch + 1 < NC){
            int nb = (ch + 1) & 1;
            const bf16* Ag = A + (size_t)m0*K + (ch+1)*32;
            #pragma unroll
            for (int i = 0; i < 2; i++){
                int row = prow + i*64;
                cp16(sbase + (uint32_t)(nb*5120 + row*PITCH + psg*8)*2, Ag + (size_t)row*K + psg*8);
            }
            const bf16* Bg = WT + (size_t)n0*K + (ch+1)*32;
            #pragma unroll
            for (int i = 0; i < NT/64; i++){
                int row = prow + i*64;
                cp16(sbase + (uint32_t)(10240 + nb*NT*PITCH + row*PITCH + psg*8)*2, Bg + (size_t)row*K + psg*8);
            }
            CP_COMMIT();
            CP_WAIT1();
        } else {
            CP_WAIT0();
        }
        __syncthreads();

        const bf16* As = sm + buf*5120;
        const bf16* Bs = sm + 10240 + buf*NT*PITCH;
        int g = lane >> 2, tid4 = lane & 3;
        #pragma unroll
        for (int kk = 0; kk < 2; kk++){
            int cb = kk*16 + tid4*2;
            uint32_t af[4][4];
            #pragma unroll
            for (int mi = 0; mi < 4; mi++){
                int r = wm + mi*16 + g;
                af[mi][0] = *(const uint32_t*)&As[r*PITCH + cb];
                af[mi][1] = *(const uint32_t*)&As[(r+8)*PITCH + cb];
                af[mi][2] = *(const uint32_t*)&As[r*PITCH + cb + 8];
                af[mi][3] = *(const uint32_t*)&As[(r+8)*PITCH + cb + 8];
            }
            uint32_t bfr[NFRAG][2];
            #pragma unroll
            for (int nj = 0; nj < NFRAG; nj++){
                int rn = wn + nj*8 + g;
                bfr[nj][0] = *(const uint32_t*)&Bs[rn*PITCH + cb];
                bfr[nj][1] = *(const uint32_t*)&Bs[rn*PITCH + cb + 8];
            }
            #pragma unroll
            for (int mi = 0; mi < 4; mi++)
                #pragma unroll
                for (int nj = 0; nj < NFRAG; nj++)
                    mma_bf16(acc[mi][nj], af[mi], bfr[nj]);
        }
        __syncthreads();
    }

    // epilogue
    int g = lane >> 2, cpair = (lane & 3) * 2;
    #pragma unroll
    for (int mi = 0; mi < 4; mi++){
        #pragma unroll
        for (int half = 0; half < 2; half++){
            int m = m0 + wm + mi*16 + g + half*8;
            #pragma unroll
            for (int nj = 0; nj < NFRAG; nj++){
                int n = n0 + wn + nj*8 + cpair;
                float v0 = acc[mi][nj][half*2 + 0];
                float v1 = acc[mi][nj][half*2 + 1];
                if (bias){ v0 += bias[n]; v1 += bias[n+1]; }
                if (RESID){
                    const float* rp = resid + (size_t)m*Nn + n;
                    v0 += rp[0]; v1 += rp[1];
                }
                if (GELU){ v0 = gelu_f(v0); v1 = gelu_f(v1); }
                if (OUTBF16){
                    __nv_bfloat162 pk;
                    pk.x = __float2bfloat16(v0); pk.y = __float2bfloat16(v1);
                    *(__nv_bfloat162*)((bf16*)Cc + (size_t)m*Nn + n) = pk;
                } else {
                    *(float2*)((float*)Cc + (size_t)m*Nn + n) = make_float2(v0, v1);
                }
            }
        }
    }
}

// ---------------- K1: row/col means of x ----------------
__global__ void k_mean(const float* __restrict__ x){
    int bc = blockIdx.x;
    __shared__ float s[64][65];
    const float* p = x + (size_t)bc*4096;
    for (int i = threadIdx.x; i < 4096; i += 256) s[i>>6][i&63] = p[i];
    __syncthreads();
    int t = threadIdx.x;
    if (t < 64){
        float su = 0.f;
        #pragma unroll 8
        for (int w = 0; w < 64; w++) su += s[t][w];
        g_xh[bc*64 + t] = su * (1.0f/64.0f);
    } else if (t < 128){
        int w = t - 64;
        float su = 0.f;
        #pragma unroll 8
        for (int h = 0; h < 64; h++) su += s[h][w];
        g_xw[bc*64 + w] = su * (1.0f/64.0f);
    }
}

// ---------------- K2: dwconv1d(k=7,p=3) + GroupNorm(16) + ReLU ----------------
__global__ void k_sdam(const float* __restrict__ w7,
                       const float* __restrict__ gnw, const float* __restrict__ gnb){
    int id = blockIdx.x;
    int which = id & 1;
    int g = (id >> 1) & 15;
    int b = id >> 5;
    float* src = which ? g_xw : g_xh;
    __shared__ float si[16][64];
    __shared__ float so[16][64];
    __shared__ float r1[256], r2[256];
    int base = (b*256 + g*16) * 64;
    for (int i = threadIdx.x; i < 1024; i += 256) si[i>>6][i&63] = src[base + i];
    __syncthreads();
    float p1 = 0.f, p2 = 0.f;
    for (int i = threadIdx.x; i < 1024; i += 256){
        int c = i >> 6, l = i & 63;
        const float* wk = w7 + (g*16 + c)*7;
        float acc = 0.f;
        #pragma unroll
        for (int k = 0; k < 7; k++){
            int ll = l - 3 + k;
            if (ll >= 0 && ll < 64) acc += si[c][ll] * wk[k];
        }
        so[c][l] = acc;
        p1 += acc; p2 += acc*acc;
    }
    r1[threadIdx.x] = p1; r2[threadIdx.x] = p2;
    __syncthreads();
    for (int st = 128; st > 0; st >>= 1){
        if (threadIdx.x < st){ r1[threadIdx.x] += r1[threadIdx.x+st]; r2[threadIdx.x] += r2[threadIdx.x+st]; }
        __syncthreads();
    }
    float mean = r1[0] * (1.0f/1024.0f);
    float var  = r2[0] * (1.0f/1024.0f) - mean*mean;
    float iv = rsqrtf(var + 1e-5f);
    for (int i = threadIdx.x; i < 1024; i += 256){
        int c = i >> 6, l = i & 63;
        float v = (so[c][l] - mean) * iv * gnw[g*16 + c] + gnb[g*16 + c];
        src[base + i] = fmaxf(v, 0.f);
    }
}

// ---------------- K3: gate x by xh*xw and transpose to tokens (g_res fp32) ----------------
__global__ void k_gate(const float* __restrict__ x){
    int b = blockIdx.z >> 6, h = blockIdx.z & 63;
    int c0 = blockIdx.y * 32, w0 = blockIdx.x * 32;
    __shared__ float t2[32][33];
    int tx = threadIdx.x, ty = threadIdx.y;
    for (int r = ty; r < 32; r += 8){
        int c = c0 + r;
        int w = w0 + tx;
        t2[r][tx] = x[((size_t)(b*256 + c)*64 + h)*64 + w]
                  * g_xh[(b*256 + c)*64 + h] * g_xw[(b*256 + c)*64 + w];
    }
    __syncthreads();
    for (int r = ty; r < 32; r += 8){
        int w = w0 + r;
        g_res[((size_t)(b*4096) + h*64 + w)*256 + c0 + tx] = t2[tx][r];
    }
}

// ---------------- token LN over 256 (warp per token), bf16 out ----------------
__global__ void k_ln256(const float* __restrict__ in, bf16* __restrict__ out,
                        const float* __restrict__ w, const float* __restrict__ bb, float eps){
    int token = blockIdx.x*8 + (threadIdx.x >> 5);
    int lane = threadIdx.x & 31;
    const float* p = in + (size_t)token*256;
    float s = 0.f, q = 0.f;
    #pragma unroll
    for (int i = lane; i < 256; i += 32){ float v = p[i]; s += v; q += v*v; }
    #pragma unroll
    for (int off = 16; off > 0; off >>= 1){
        s += __shfl_xor_sync(0xffffffff, s, off);
        q += __shfl_xor_sync(0xffffffff, q, off);
    }
    float m = s * (1.0f/256.0f);
    float var = q * (1.0f/256.0f) - m*m;
    float iv = rsqrtf(var + eps);
    #pragma unroll
    for (int i = lane; i < 256; i += 32)
        out[(size_t)token*256 + i] = __float2bfloat16((p[i] - m) * iv * w[i] + bb[i]);
}

// ---------------- K5: reduction conv chain per (b,c): 64->16->4, then dw 3x3 ----------------
__global__ void k_red(const float* __restrict__ red_w, const float* __restrict__ red_b,
                      const float* __restrict__ dw_w, const float* __restrict__ dw_b){
    int bc = blockIdx.x;
    int b = bc >> 8, c = bc & 255;
    __shared__ float rw[16];
    __shared__ float dwv[9];
    __shared__ float o1[16][16];
    __shared__ float o2[4][4];
    int t = threadIdx.x;
    if (t < 16) rw[t] = red_w[c*16 + t];
    if (t >= 16 && t < 25) dwv[t-16] = dw_w[c*9 + (t-16)];
    __syncthreads();
    float rb = red_b[c];
    {
        int u = t >> 4, v = t & 15;
        float acc = 0.f;
        #pragma unroll
        for (int p = 0; p < 4; p++)
            #pragma unroll
            for (int q = 0; q < 4; q++)
                acc += __bfloat162float(g_tln[((size_t)(b*4096) + (4*u+p)*64 + (4*v+q))*256 + c]) * rw[p*4+q];
        o1[u][v] = acc + rb;
    }
    __syncthreads();
    if (t < 16){
        int y = t >> 2, x = t & 3;
        float acc = 0.f;
        #pragma unroll
        for (int p = 0; p < 4; p++)
            #pragma unroll
            for (int q = 0; q < 4; q++)
                acc += o1[4*y+p][4*x+q] * rw[p*4+q];
        o2[y][x] = acc + rb;
    }
    __syncthreads();
    if (t < 16){
        int y = t >> 2, x = t & 3;
        float acc = dw_b[c];
        #pragma unroll
        for (int dy = -1; dy <= 1; dy++)
            #pragma unroll
            for (int dx = -1; dx <= 1; dx++){
                int yy = y+dy, xx = x+dx;
                if (yy >= 0 && yy < 4 && xx >= 0 && xx < 4)
                    acc += o2[yy][xx] * dwv[(dy+1)*3 + dx+1];
            }
        g_red[(b*256 + c)*16 + t] = acc;
    }
}

// ---------------- K6: per batch — 1x1 conv + LN + gelu, k/v proj, CPE ----------------
__global__ void k_small(const float* __restrict__ conv_w, const float* __restrict__ conv_b,
                        const float* __restrict__ na_w, const float* __restrict__ na_b,
                        const float* __restrict__ k_w, const float* __restrict__ v_w,
                        const float* __restrict__ cpe_w, const float* __restrict__ cpe_b){
    int b = blockIdx.x;
    int tid = threadIdx.x;
    __shared__ float yr[256][16];
    __shared__ float xr[16][128];
    __shared__ float vs[16][256];
    __shared__ float mu2[16], iv2[16];
    for (int i = tid; i < 4096; i += 128) yr[i>>4][i&15] = g_red[b*4096 + i];
    __syncthreads();
    {
        float tmp[16];
        float cb = conv_b[tid];
        #pragma unroll
        for (int nr = 0; nr < 16; nr++) tmp[nr] = cb;
        for (int c = 0; c < 256; c++){
            float wv = conv_w[tid*256 + c];
            #pragma unroll
            for (int nr = 0; nr < 16; nr++) tmp[nr] += yr[c][nr] * wv;
        }
        #pragma unroll
        for (int nr = 0; nr < 16; nr++) xr[nr][tid] = tmp[nr];
    }
    __syncthreads();
    if (tid < 16){
        float s = 0.f, q = 0.f;
        for (int o = 0; o < 128; o++){ float v = xr[tid][o]; s += v; q += v*v; }
        float m = s * (1.0f/128.0f);
        float var = q * (1.0f/128.0f) - m*m;
        mu2[tid] = m; iv2[tid] = rsqrtf(var + 1e-5f);
    }
    __syncthreads();
    #pragma unroll
    for (int nr = 0; nr < 16; nr++){
        float v = (xr[nr][tid] - mu2[nr]) * iv2[nr] * na_w[tid] + na_b[tid];
        xr[nr][tid] = gelu_f(v);
    }
    __syncthreads();
    {
        float ka[16];
        #pragma unroll
        for (int nr = 0; nr < 16; nr++) ka[nr] = 0.f;
        for (int c = 0; c < 128; c++){
            float wv = k_w[c*128 + tid];
            #pragma unroll
            for (int nr = 0; nr < 16; nr++) ka[nr] += xr[nr][c] * wv;
        }
        #pragma unroll
        for (int nr = 0; nr < 16; nr++) g_k[(b*16 + nr)*128 + tid] = ka[nr];
    }
    for (int half = 0; half < 2; half++){
        int o3 = half*128 + tid;
        float va[16];
        #pragma unroll
        for (int nr = 0; nr < 16; nr++) va[nr] = 0.f;
        for (int c = 0; c < 128; c++){
            float wv = v_w[c*256 + o3];
            #pragma unroll
            for (int nr = 0; nr < 16; nr++) va[nr] += xr[nr][c] * wv;
        }
        #pragma unroll
        for (int nr = 0; nr < 16; nr++) vs[nr][o3] = va[nr];
    }
    __syncthreads();
    for (int half = 0; half < 2; half++){
        int cc = half*128 + tid;
        float w9[9];
        #pragma unroll
        for (int j = 0; j < 9; j++) w9[j] = cpe_w[cc*9 + j];
        float cb = cpe_b[cc];
        #pragma unroll
        for (int nr = 0; nr < 16; nr++){
            int y = nr >> 2, x = nr & 3;
            float acc = cb;
            #pragma unroll
            for (int dy = -1; dy <= 1; dy++)
                #pragma unroll
                for (int dx = -1; dx <= 1; dx++){
                    int yy = y+dy, xx = x+dx;
                    if (yy >= 0 && yy < 4 && xx >= 0 && xx < 4)
                        acc += vs[yy*4+xx][cc] * w9[(dy+1)*3 + dx+1];
                }
            g_v[(b*16 + nr)*256 + cc] = vs[nr][cc] + acc;
        }
    }
}

// ---------------- K7: attention (fused, Nr=16), bf16 out ----------------
__global__ void k_attn(){
    __shared__ float ks[8][16][16];
    __shared__ float vs2[16][256];
    int b  = blockIdx.x >> 7;
    int tb = (blockIdx.x & 127) * 32;
    for (int i = threadIdx.x; i < 2048; i += 256){
        int m = i >> 7, j = i & 127;
        ks[j>>4][m][j&15] = g_k[(b*16 + m)*128 + j];
    }
    for (int i = threadIdx.x; i < 4096; i += 256){
        int m = i >> 8, cc2 = i & 255;
        vs2[m][cc2] = g_v[(b*16 + m)*256 + cc2];
    }
    __syncthreads();
    int h = threadIdx.x >> 5;
    int tk = threadIdx.x & 31;
    size_t n = (size_t)b*4096 + tb + tk;
    float qv[16];
    const float* qp = g_q + n*128 + h*16;
    #pragma unroll
    for (int d = 0; d < 16; d++) qv[d] = qp[d];
    float s[16];
    float mx = -1e30f;
    #pragma unroll
    for (int m = 0; m < 16; m++){
        float dot = 0.f;
        #pragma unroll
        for (int d = 0; d < 16; d++) dot += qv[d] * ks[h][m][d];
        s[m] = dot * 0.25f;
        mx = fmaxf(mx, s[m]);
    }
    float sum = 0.f;
    #pragma unroll
    for (int m = 0; m < 16; m++){ s[m] = expf(s[m] - mx); sum += s[m]; }
    float inv = 1.0f / sum;
    bf16* op = g_o + n*256 + h*32;
    #pragma unroll
    for (int d2 = 0; d2 < 32; d2++){
        float a = 0.f;
        #pragma unroll
        for (int m = 0; m < 16; m++) a += s[m] * vs2[m][h*32 + d2];
        op[d2] = __float2bfloat16(a * inv);
    }
}

// ---------------- gnorm: LN(512) over x2 half of g_h, token-layout bf16 out (coalesced) ----------------
__global__ void k_gnorm(const float* __restrict__ gw, const float* __restrict__ gb){
    int token = blockIdx.x*8 + (threadIdx.x >> 5);
    int lane = threadIdx.x & 31;
    const bf16* p = g_h + (size_t)token*1024 + 512;
    float s = 0.f, q = 0.f;
    float vals[16];
    #pragma unroll
    for (int j = 0; j < 16; j++){
        float v = __bfloat162float(p[lane + j*32]);
        vals[j] = v; s += v; q += v*v;
    }
    #pragma unroll
    for (int off = 16; off > 0; off >>= 1){
        s += __shfl_xor_sync(0xffffffff, s, off);
        q += __shfl_xor_sync(0xffffffff, q, off);
    }
    float m = s * (1.0f/512.0f);
    float var = q * (1.0f/512.0f) - m*m;
    float iv = rsqrtf(var + 1e-5f);
    bf16* o = g_x2t + (size_t)token*512;
    #pragma unroll
    for (int j = 0; j < 16; j++){
        int i = lane + j*32;
        o[i] = __float2bfloat16((vals[j] - m) * iv * gw[i] + gb[i]);
    }
}

// ---------------- transpose x2t (token) -> x2i (image), bf16 32x32 tiles ----------------
__global__ void k_trx2(){
    int b = blockIdx.z;
    int c0 = blockIdx.y * 32, n0 = blockIdx.x * 32;
    __shared__ bf16 tl[32][33];
    int tx = threadIdx.x, ty = threadIdx.y;
    for (int r = ty; r < 32; r += 8)
        tl[r][tx] = g_x2t[((size_t)(b*4096) + n0 + r)*512 + c0 + tx];
    __syncthreads();
    for (int r = ty; r < 32; r += 8)
        g_x2i[((size_t)(b*512 + c0 + r))*4096 + n0 + tx] = tl[tx][r];
}

// ---------------- depthwise 3x3 on 64x64, image layout, bf16 ----------------
__global__ void k_gconv(const float* __restrict__ gw, const float* __restrict__ gb){
    int bc = blockIdx.x;
    int c = bc & 511;
    const bf16* src = g_x2i + (size_t)bc*4096;
    bf16* dst = g_x2c + (size_t)bc*4096;
    __shared__ float tl[66][66];
    for (int i = threadIdx.x; i < 66*66; i += 256){
        int y = i / 66 - 1, x = i % 66 - 1;
        tl[y+1][x+1] = (y >= 0 && y < 64 && x >= 0 && x < 64) ? __bfloat162float(src[y*64 + x]) : 0.f;
    }
    __syncthreads();
    float w9[9];
    #pragma unroll
    for (int j = 0; j < 9; j++) w9[j] = gw[c*9 + j];
    float bias = gb[c];
    for (int i = threadIdx.x; i < 4096; i += 256){
        int y = i >> 6, x = i & 63;
        float a = bias;
        #pragma unroll
        for (int dy = 0; dy < 3; dy++)
            #pragma unroll
            for (int dx = 0; dx < 3; dx++)
                a += tl[y+dy][x+dx] * w9[dy*3 + dx];
        dst[i] = __float2bfloat16(a);
    }
}

// ---------------- transpose x2c back to tokens and gate with x1 -> g_gate bf16 ----------------
__global__ void k_gatemlp(){
    int b = blockIdx.z;
    int c0 = blockIdx.y * 32, n0 = blockIdx.x * 32;
    int tx = threadIdx.x, ty = threadIdx.y;
    __shared__ bf16 tl[32][33];
    for (int r = ty; r < 32; r += 8)
        tl[r][tx] = g_x2c[((size_t)(b*512 + c0 + r))*4096 + n0 + tx];
    __syncthreads();
    for (int r = ty; r < 32; r += 8){
        size_t tok = (size_t)b*4096 + n0 + r;
        float x1 = __bfloat162float(g_h[tok*1024 + c0 + tx]);
        float x2 = __bfloat162float(tl[tx][r]);
        g_gate[tok*512 + c0 + tx] = __float2bfloat16(x1 * x2);
    }
}

// ---------------- final: transpose fc2 token-layout temp -> [B,C,H,W] out ----------------
__global__ void k_out(const float* __restrict__ otmp, float* __restrict__ out){
    int b = blockIdx.z;
    int c0 = blockIdx.y * 32, n0 = blockIdx.x * 32;
    __shared__ float tl[32][33];
    int tx = threadIdx.x, ty = threadIdx.y;
    for (int r = ty; r < 32; r += 8)
        tl[r][tx] = otmp[((size_t)(b*4096) + n0 + r)*256 + c0 + tx];
    __syncthreads();
    for (int r = ty; r < 32; r += 8)
        out[((size_t)(b*256 + c0 + r))*4096 + n0 + tx] = tl[tx][r];
}

// ---------------- launcher ----------------
#define SMEM_NT128 ((20480 + 128*160))
#define SMEM_NT256 ((20480 + 256*160))

extern "C" void kernel_launch(void* const* d_in, const int* in_sizes, int n_in,
                              void* d_out, int out_size){
    const float* x        = (const float*)d_in[0];
    const float* sda_w    = (const float*)d_in[1];
    const float* sda_gnw  = (const float*)d_in[2];
    const float* sda_gnb  = (const float*)d_in[3];
    const float* n1w      = (const float*)d_in[4];
    const float* n1b      = (const float*)d_in[5];
    const float* red_w    = (const float*)d_in[6];
    const float* red_b    = (const float*)d_in[7];
    const float* dw_w     = (const float*)d_in[8];
    const float* dw_b     = (const float*)d_in[9];
    const float* conv_w   = (const float*)d_in[10];
    const float* conv_b   = (const float*)d_in[11];
    const float* na_w     = (const float*)d_in[12];
    const float* na_b     = (const float*)d_in[13];
    const float* q_w      = (const float*)d_in[14];
    const float* k_w      = (const float*)d_in[15];
    const float* v_w      = (const float*)d_in[16];
    const float* cpe_w    = (const float*)d_in[17];
    const float* cpe_b    = (const float*)d_in[18];
    const float* proj_w   = (const float*)d_in[19];
    const float* proj_b   = (const float*)d_in[20];
    const float* n2w      = (const float*)d_in[21];
    const float* n2b      = (const float*)d_in[22];
    const float* fc1_w    = (const float*)d_in[23];
    const float* fc1_b    = (const float*)d_in[24];
    const float* gn_w     = (const float*)d_in[25];
    const float* gn_b     = (const float*)d_in[26];
    const float* gc_w     = (const float*)d_in[27];
    const float* gc_b     = (const float*)d_in[28];
    const float* fc2_w    = (const float*)d_in[29];
    const float* fc2_b    = (const float*)d_in[30];
    float* out = (float*)d_out;

    float *p_res, *p_q;
    bf16 *p_tln, *p_o, *p_gate, *p_h;
    bf16 *p_qT, *p_projT, *p_fc1T, *p_fc2T;
    cudaGetSymbolAddress((void**)&p_res, g_res);
    cudaGetSymbolAddress((void**)&p_tln, g_tln);
    cudaGetSymbolAddress((void**)&p_q,   g_q);
    cudaGetSymbolAddress((void**)&p_o,   g_o);
    cudaGetSymbolAddress((void**)&p_gate,g_gate);
    cudaGetSymbolAddress((void**)&p_h,   g_h);
    cudaGetSymbolAddress((void**)&p_qT,  g_qT);
    cudaGetSymbolAddress((void**)&p_projT, g_projT);
    cudaGetSymbolAddress((void**)&p_fc1T, g_fc1T);
    cudaGetSymbolAddress((void**)&p_fc2T, g_fc2T);
    float* p_otmp = (float*)p_h;    // fc2 fp32 temp reuses g_h (g_h no longer needed then)

    cudaFuncSetAttribute(k_gemm_bf<128,false,false,false>, cudaFuncAttributeMaxDynamicSharedMemorySize, SMEM_NT128);
    cudaFuncSetAttribute(k_gemm_bf<256,false,true,false>,  cudaFuncAttributeMaxDynamicSharedMemorySize, SMEM_NT256);
    cudaFuncSetAttribute(k_gemm_bf<256,true,false,true>,   cudaFuncAttributeMaxDynamicSharedMemorySize, SMEM_NT256);

    // 0. weight transposes -> bf16 [N,K]
    k_tr<<<dim3(CRD/32, CC/32), dim3(32,8)>>>(q_w,    p_qT,   CC,   CRD);
    k_tr<<<dim3(CC/32,  CC/32), dim3(32,8)>>>(proj_w, p_projT, CC,  CC);
    k_tr<<<dim3(HID/32, CC/32), dim3(32,8)>>>(fc1_w,  p_fc1T, CC,   HID);
    k_tr<<<dim3(CC/32, HALF/32), dim3(32,8)>>>(fc2_w, p_fc2T, HALF, CC);

    // 1. means
    k_mean<<<BB*CC, 256>>>(x);
    // 2. SDAM conv1d + GN + relu
    k_sdam<<<BB*16*2, 256>>>(sda_w, sda_gnw, sda_gnb);
    // 3. gate + to tokens (fp32 residual)
    k_gate<<<dim3(2, 8, BB*HH), dim3(32, 8)>>>(x);
    // 4. LN1 -> bf16
    k_ln256<<<BN/8, 256>>>(p_res, p_tln, n1w, n1b, 1e-6f);
    // 5. reduction conv chain
    k_red<<<BB*CC, 256>>>(red_w, red_b, dw_w, dw_b);
    // 6. small per-batch stage
    k_small<<<BB, 128>>>(conv_w, conv_b, na_w, na_b, k_w, v_w, cpe_w, cpe_b);
    // 7. Q = tln @ q_w
    k_gemm_bf<128,false,false,false><<<dim3(1, BN/128), 256, SMEM_NT128>>>(p_tln, p_qT, nullptr, nullptr, p_q, BN, CRD, CC);
    // 8. attention -> bf16
    k_attn<<<BN/32, 256>>>();
    // 9. proj + residual -> fp32 g_res
    k_gemm_bf<256,false,true,false><<<dim3(1, BN/128), 256, SMEM_NT256>>>(p_o, p_projT, proj_b, p_res, p_res, BN, CC, CC);
    // 10. LN2 -> bf16
    k_ln256<<<BN/8, 256>>>(p_res, p_tln, n2w, n2b, 1e-6f);
    // 11. fc1 + gelu -> bf16 g_h
    k_gemm_bf<256,true,false,true><<<dim3(HID/256, BN/128), 256, SMEM_NT256>>>(p_tln, p_fc1T, fc1_b, nullptr, p_h, BN, HID, CC);
    // 12. gnorm -> token-layout bf16 (coalesced)
    k_gnorm<<<BN/8, 256>>>(gn_w, gn_b);
    // 13. transpose to image layout
    k_trx2<<<dim3(NN/32, HALF/32, BB), dim3(32, 8)>>>();
    // 14. depthwise 3x3
    k_gconv<<<BB*HALF, 256>>>(gc_w, gc_b);
    // 15. transpose back + gate with x1 -> bf16
    k_gatemlp<<<dim3(NN/32, HALF/32, BB), dim3(32, 8)>>>();
    // 16. fc2 + bias + residual -> fp32 token-layout temp
    k_gemm_bf<256,false,true,false><<<dim3(1, BN/128), 256, SMEM_NT256>>>(p_gate, p_fc2T, fc2_b, p_res, p_otmp, BN, CC, HALF);
    // 17. final transpose to [B,C,H,W]
    k_out<<<dim3(NN/32, CC/32, BB), dim3(32, 8)>>>(p_otmp, out);
}

// round 12
// speedup vs baseline: 1.5373x; 1.5373x over previous
#include <cuda_runtime.h>
#include <cuda_bf16.h>
#include <math.h>
#include <stdint.h>

// ---------------- constants ----------------
#define BB 16
#define CC 256
#define HH 64
#define WW 64
#define NN 4096            // tokens per batch
#define BN (BB*NN)         // 65536 total tokens
#define CRD 128
#define NHD 8
#define NRD 16             // reduced tokens (4x4)
#define HID 1024
#define HALF 512

typedef __nv_bfloat16 bf16;

// ---------------- scratch (device globals; no allocation) ----------------
__device__ float g_xh[BB*CC*HH];
__device__ float g_xw[BB*CC*WW];
__device__ float g_res[(size_t)BN*CC];      // gated tokens (fp32 residual)
__device__ bf16  g_tln[(size_t)BN*CC];      // LN1/LN2 out (bf16, GEMM A)
__device__ float g_q[(size_t)BN*CRD];
__device__ bf16  g_o[(size_t)BN*CC];        // attention out (bf16, GEMM A)
__device__ float g_red[BB*CC*NRD];
__device__ float g_k[BB*NRD*CRD];
__device__ float g_v[BB*NRD*CC];
__device__ bf16  g_h[(size_t)BN*HID];       // fc1 out (bf16); reused as fc2 fp32 temp
__device__ bf16  g_x2t[(size_t)BN*HALF];    // gnormed x2, token layout
__device__ bf16  g_x2i[(size_t)BN*HALF];    // image layout
__device__ bf16  g_x2c[(size_t)BN*HALF];    // after gconv, image layout
__device__ bf16  g_gate[(size_t)BN*HALF];   // x1*x2 token layout (GEMM A)
// transposed bf16 weights [N,K]
__device__ bf16 g_qT[CRD*CC];
__device__ bf16 g_projT[CC*CC];
__device__ bf16 g_fc1T[HID*CC];
__device__ bf16 g_fc2T[CC*HALF];

__device__ __forceinline__ float gelu_f(float v){
    return 0.5f * v * (1.0f + erff(v * 0.70710678118654752f));
}
__device__ __forceinline__ uint32_t smem_u32(const void* p){
    uint32_t a;
    asm("{ .reg .u64 t; cvta.to.shared.u64 t, %1; cvt.u32.u64 %0, t; }" : "=r"(a) : "l"(p));
    return a;
}
__device__ __forceinline__ void cp16(uint32_t dst, const void* src){
    asm volatile("cp.async.cg.shared.global [%0], [%1], 16;" :: "r"(dst), "l"(src));
}
#define CP_COMMIT() asm volatile("cp.async.commit_group;" ::: "memory")
#define CP_WAIT0()  asm volatile("cp.async.wait_group 0;" ::: "memory")
#define CP_WAIT1()  asm volatile("cp.async.wait_group 1;" ::: "memory")

__device__ __forceinline__ void mma_bf16(float* c, const uint32_t* a, const uint32_t* b){
    asm volatile(
        "mma.sync.aligned.m16n8k16.row.col.f32.bf16.bf16.f32 "
        "{%0,%1,%2,%3}, {%4,%5,%6,%7}, {%8,%9}, {%0,%1,%2,%3};"
        : "+f"(c[0]), "+f"(c[1]), "+f"(c[2]), "+f"(c[3])
        : "r"(a[0]), "r"(a[1]), "r"(a[2]), "r"(a[3]), "r"(b[0]), "r"(b[1]));
}

// ---------------- weight transpose to bf16: WT[n*K+k] = bf16(W[k*N+n]) ----------------
__global__ void k_tr(const float* __restrict__ W, bf16* __restrict__ WT, int K, int Nn){
    __shared__ float t[32][33];
    int k0 = blockIdx.y*32, n0 = blockIdx.x*32;
    int tx = threadIdx.x, ty = threadIdx.y;
    for (int r = ty; r < 32; r += 8)
        t[r][tx] = W[(size_t)(k0+r)*Nn + n0 + tx];
    __syncthreads();
    for (int r = ty; r < 32; r += 8)
        WT[(size_t)(n0+r)*K + k0 + tx] = __float2bfloat16(t[tx][r]);
}

// ---------------- bf16 mma.sync GEMM: C[M,N] = A[M,K] * WT[N,K]^T ----------------
// CTA 128x128, warp tile 64x32, K chunk 32 bf16, cp.async double buffer, 2 CTAs/SM.
// smem (bf16 units): A0=0, A1=5120, B0=10240, B1=15360. pitch 40 bf16 = 80B.
#define PITCH 40
#define GEMM_SMEM 40960
template<bool GELU, bool RESID, bool OUTBF16>
__global__ __launch_bounds__(256, 2) void k_gemm_bf(
        const bf16* __restrict__ A, const bf16* __restrict__ WT,
        const float* __restrict__ bias, const float* __restrict__ resid,
        void* __restrict__ Cc, int M, int Nn, int K){
    extern __shared__ bf16 sm[];
    uint32_t sbase = smem_u32(sm);
    int tid = threadIdx.x, wid = tid >> 5, lane = tid & 31;
    int m0 = blockIdx.y * 128, n0 = blockIdx.x * 128;
    int wm = (wid & 1) * 64;
    int wn = (wid >> 1) * 32;

    float acc[4][4][4];
    #pragma unroll
    for (int i = 0; i < 4; i++)
        #pragma unroll
        for (int j = 0; j < 4; j++)
            #pragma unroll
            for (int q = 0; q < 4; q++) acc[i][j][q] = 0.f;

    int NC = K >> 5;
    int prow = tid >> 2, psg = tid & 3;    // 64 rows per pass, 4 x 16B segments per row (32 bf16)

    // prefetch chunk 0
    {
        const bf16* Ag = A  + (size_t)m0*K;
        const bf16* Bg = WT + (size_t)n0*K;
        #pragma unroll
        for (int i = 0; i < 2; i++){
            int row = prow + i*64;
            cp16(sbase + (uint32_t)(row*PITCH + psg*8)*2,         Ag + (size_t)row*K + psg*8);
            cp16(sbase + (uint32_t)(10240 + row*PITCH + psg*8)*2, Bg + (size_t)row*K + psg*8);
        }
        CP_COMMIT();
    }

    for (int ch = 0; ch < NC; ch++){
        int buf = ch & 1;
        if (ch + 1 < NC){
            int nb = (ch + 1) & 1;
            const bf16* Ag = A  + (size_t)m0*K + (ch+1)*32;
            const bf16* Bg = WT + (size_t)n0*K + (ch+1)*32;
            #pragma unroll
            for (int i = 0; i < 2; i++){
                int row = prow + i*64;
                cp16(sbase + (uint32_t)(nb*5120 + row*PITCH + psg*8)*2,         Ag + (size_t)row*K + psg*8);
                cp16(sbase + (uint32_t)(10240 + nb*5120 + row*PITCH + psg*8)*2, Bg + (size_t)row*K + psg*8);
            }
            CP_COMMIT();
            CP_WAIT1();
        } else {
            CP_WAIT0();
        }
        __syncthreads();

        const bf16* As = sm + buf*5120;
        const bf16* Bs = sm + 10240 + buf*5120;
        int g = lane >> 2, tid4 = lane & 3;
        #pragma unroll
        for (int kk = 0; kk < 2; kk++){
            int cb = kk*16 + tid4*2;
            uint32_t af[4][4];
            #pragma unroll
            for (int mi = 0; mi < 4; mi++){
                int r = wm + mi*16 + g;
                af[mi][0] = *(const uint32_t*)&As[r*PITCH + cb];
                af[mi][1] = *(const uint32_t*)&As[(r+8)*PITCH + cb];
                af[mi][2] = *(const uint32_t*)&As[r*PITCH + cb + 8];
                af[mi][3] = *(const uint32_t*)&As[(r+8)*PITCH + cb + 8];
            }
            uint32_t bfr[4][2];
            #pragma unroll
            for (int nj = 0; nj < 4; nj++){
                int rn = wn + nj*8 + g;
                bfr[nj][0] = *(const uint32_t*)&Bs[rn*PITCH + cb];
                bfr[nj][1] = *(const uint32_t*)&Bs[rn*PITCH + cb + 8];
            }
            #pragma unroll
            for (int mi = 0; mi < 4; mi++)
                #pragma unroll
                for (int nj = 0; nj < 4; nj++)
                    mma_bf16(acc[mi][nj], af[mi], bfr[nj]);
        }
        __syncthreads();
    }

    // epilogue
    int g = lane >> 2, cpair = (lane & 3) * 2;
    #pragma unroll
    for (int mi = 0; mi < 4; mi++){
        #pragma unroll
        for (int half = 0; half < 2; half++){
            int m = m0 + wm + mi*16 + g + half*8;
            #pragma unroll
            for (int nj = 0; nj < 4; nj++){
                int n = n0 + wn + nj*8 + cpair;
                float v0 = acc[mi][nj][half*2 + 0];
                float v1 = acc[mi][nj][half*2 + 1];
                if (bias){ v0 += bias[n]; v1 += bias[n+1]; }
                if (RESID){
                    const float* rp = resid + (size_t)m*Nn + n;
                    v0 += rp[0]; v1 += rp[1];
                }
                if (GELU){ v0 = gelu_f(v0); v1 = gelu_f(v1); }
                if (OUTBF16){
                    __nv_bfloat162 pk;
                    pk.x = __float2bfloat16(v0); pk.y = __float2bfloat16(v1);
                    *(__nv_bfloat162*)((bf16*)Cc + (size_t)m*Nn + n) = pk;
                } else {
                    *(float2*)((float*)Cc + (size_t)m*Nn + n) = make_float2(v0, v1);
                }
            }
        }
    }
}

// ---------------- K1: row/col means of x ----------------
__global__ void k_mean(const float* __restrict__ x){
    int bc = blockIdx.x;
    __shared__ float s[64][65];
    const float* p = x + (size_t)bc*4096;
    for (int i = threadIdx.x; i < 4096; i += 256) s[i>>6][i&63] = p[i];
    __syncthreads();
    int t = threadIdx.x;
    if (t < 64){
        float su = 0.f;
        #pragma unroll 8
        for (int w = 0; w < 64; w++) su += s[t][w];
        g_xh[bc*64 + t] = su * (1.0f/64.0f);
    } else if (t < 128){
        int w = t - 64;
        float su = 0.f;
        #pragma unroll 8
        for (int h = 0; h < 64; h++) su += s[h][w];
        g_xw[bc*64 + w] = su * (1.0f/64.0f);
    }
}

// ---------------- K2: dwconv1d(k=7,p=3) + GroupNorm(16) + ReLU ----------------
__global__ void k_sdam(const float* __restrict__ w7,
                       const float* __restrict__ gnw, const float* __restrict__ gnb){
    int id = blockIdx.x;
    int which = id & 1;
    int g = (id >> 1) & 15;
    int b = id >> 5;
    float* src = which ? g_xw : g_xh;
    __shared__ float si[16][64];
    __shared__ float so[16][64];
    __shared__ float r1[256], r2[256];
    int base = (b*256 + g*16) * 64;
    for (int i = threadIdx.x; i < 1024; i += 256) si[i>>6][i&63] = src[base + i];
    __syncthreads();
    float p1 = 0.f, p2 = 0.f;
    for (int i = threadIdx.x; i < 1024; i += 256){
        int c = i >> 6, l = i & 63;
        const float* wk = w7 + (g*16 + c)*7;
        float acc = 0.f;
        #pragma unroll
        for (int k = 0; k < 7; k++){
            int ll = l - 3 + k;
            if (ll >= 0 && ll < 64) acc += si[c][ll] * wk[k];
        }
        so[c][l] = acc;
        p1 += acc; p2 += acc*acc;
    }
    r1[threadIdx.x] = p1; r2[threadIdx.x] = p2;
    __syncthreads();
    for (int st = 128; st > 0; st >>= 1){
        if (threadIdx.x < st){ r1[threadIdx.x] += r1[threadIdx.x+st]; r2[threadIdx.x] += r2[threadIdx.x+st]; }
        __syncthreads();
    }
    float mean = r1[0] * (1.0f/1024.0f);
    float var  = r2[0] * (1.0f/1024.0f) - mean*mean;
    float iv = rsqrtf(var + 1e-5f);
    for (int i = threadIdx.x; i < 1024; i += 256){
        int c = i >> 6, l = i & 63;
        float v = (so[c][l] - mean) * iv * gnw[g*16 + c] + gnb[g*16 + c];
        src[base + i] = fmaxf(v, 0.f);
    }
}

// ---------------- K3: gate x by xh*xw and transpose to tokens (g_res fp32) ----------------
__global__ void k_gate(const float* __restrict__ x){
    int b = blockIdx.z >> 6, h = blockIdx.z & 63;
    int c0 = blockIdx.y * 32, w0 = blockIdx.x * 32;
    __shared__ float t2[32][33];
    int tx = threadIdx.x, ty = threadIdx.y;
    for (int r = ty; r < 32; r += 8){
        int c = c0 + r;
        int w = w0 + tx;
        t2[r][tx] = x[((size_t)(b*256 + c)*64 + h)*64 + w]
                  * g_xh[(b*256 + c)*64 + h] * g_xw[(b*256 + c)*64 + w];
    }
    __syncthreads();
    for (int r = ty; r < 32; r += 8){
        int w = w0 + r;
        g_res[((size_t)(b*4096) + h*64 + w)*256 + c0 + tx] = t2[tx][r];
    }
}

// ---------------- token LN over 256 (warp per token), bf16 out ----------------
__global__ void k_ln256(const float* __restrict__ in, bf16* __restrict__ out,
                        const float* __restrict__ w, const float* __restrict__ bb, float eps){
    int token = blockIdx.x*8 + (threadIdx.x >> 5);
    int lane = threadIdx.x & 31;
    const float* p = in + (size_t)token*256;
    float s = 0.f, q = 0.f;
    #pragma unroll
    for (int i = lane; i < 256; i += 32){ float v = p[i]; s += v; q += v*v; }
    #pragma unroll
    for (int off = 16; off > 0; off >>= 1){
        s += __shfl_xor_sync(0xffffffff, s, off);
        q += __shfl_xor_sync(0xffffffff, q, off);
    }
    float m = s * (1.0f/256.0f);
    float var = q * (1.0f/256.0f) - m*m;
    float iv = rsqrtf(var + eps);
    #pragma unroll
    for (int i = lane; i < 256; i += 32)
        out[(size_t)token*256 + i] = __float2bfloat16((p[i] - m) * iv * w[i] + bb[i]);
}

// ---------------- K5: reduction conv chain per (b,c): 64->16->4, then dw 3x3 ----------------
__global__ void k_red(const float* __restrict__ red_w, const float* __restrict__ red_b,
                      const float* __restrict__ dw_w, const float* __restrict__ dw_b){
    int bc = blockIdx.x;
    int b = bc >> 8, c = bc & 255;
    __shared__ float rw[16];
    __shared__ float dwv[9];
    __shared__ float o1[16][16];
    __shared__ float o2[4][4];
    int t = threadIdx.x;
    if (t < 16) rw[t] = red_w[c*16 + t];
    if (t >= 16 && t < 25) dwv[t-16] = dw_w[c*9 + (t-16)];
    __syncthreads();
    float rb = red_b[c];
    {
        int u = t >> 4, v = t & 15;
        float acc = 0.f;
        #pragma unroll
        for (int p = 0; p < 4; p++)
            #pragma unroll
            for (int q = 0; q < 4; q++)
                acc += __bfloat162float(g_tln[((size_t)(b*4096) + (4*u+p)*64 + (4*v+q))*256 + c]) * rw[p*4+q];
        o1[u][v] = acc + rb;
    }
    __syncthreads();
    if (t < 16){
        int y = t >> 2, x = t & 3;
        float acc = 0.f;
        #pragma unroll
        for (int p = 0; p < 4; p++)
            #pragma unroll
            for (int q = 0; q < 4; q++)
                acc += o1[4*y+p][4*x+q] * rw[p*4+q];
        o2[y][x] = acc + rb;
    }
    __syncthreads();
    if (t < 16){
        int y = t >> 2, x = t & 3;
        float acc = dw_b[c];
        #pragma unroll
        for (int dy = -1; dy <= 1; dy++)
            #pragma unroll
            for (int dx = -1; dx <= 1; dx++){
                int yy = y+dy, xx = x+dx;
                if (yy >= 0 && yy < 4 && xx >= 0 && xx < 4)
                    acc += o2[yy][xx] * dwv[(dy+1)*3 + dx+1];
            }
        g_red[(b*256 + c)*16 + t] = acc;
    }
}

// ---------------- K6: per batch — 1x1 conv + LN + gelu, k/v proj, CPE ----------------
__global__ void k_small(const float* __restrict__ conv_w, const float* __restrict__ conv_b,
                        const float* __restrict__ na_w, const float* __restrict__ na_b,
                        const float* __restrict__ k_w, const float* __restrict__ v_w,
                        const float* __restrict__ cpe_w, const float* __restrict__ cpe_b){
    int b = blockIdx.x;
    int tid = threadIdx.x;
    __shared__ float yr[256][16];
    __shared__ float xr[16][128];
    __shared__ float vs[16][256];
    __shared__ float mu2[16], iv2[16];
    for (int i = tid; i < 4096; i += 128) yr[i>>4][i&15] = g_red[b*4096 + i];
    __syncthreads();
    {
        float tmp[16];
        float cb = conv_b[tid];
        #pragma unroll
        for (int nr = 0; nr < 16; nr++) tmp[nr] = cb;
        for (int c = 0; c < 256; c++){
            float wv = conv_w[tid*256 + c];
            #pragma unroll
            for (int nr = 0; nr < 16; nr++) tmp[nr] += yr[c][nr] * wv;
        }
        #pragma unroll
        for (int nr = 0; nr < 16; nr++) xr[nr][tid] = tmp[nr];
    }
    __syncthreads();
    if (tid < 16){
        float s = 0.f, q = 0.f;
        for (int o = 0; o < 128; o++){ float v = xr[tid][o]; s += v; q += v*v; }
        float m = s * (1.0f/128.0f);
        float var = q * (1.0f/128.0f) - m*m;
        mu2[tid] = m; iv2[tid] = rsqrtf(var + 1e-5f);
    }
    __syncthreads();
    #pragma unroll
    for (int nr = 0; nr < 16; nr++){
        float v = (xr[nr][tid] - mu2[nr]) * iv2[nr] * na_w[tid] + na_b[tid];
        xr[nr][tid] = gelu_f(v);
    }
    __syncthreads();
    {
        float ka[16];
        #pragma unroll
        for (int nr = 0; nr < 16; nr++) ka[nr] = 0.f;
        for (int c = 0; c < 128; c++){
            float wv = k_w[c*128 + tid];
            #pragma unroll
            for (int nr = 0; nr < 16; nr++) ka[nr] += xr[nr][c] * wv;
        }
        #pragma unroll
        for (int nr = 0; nr < 16; nr++) g_k[(b*16 + nr)*128 + tid] = ka[nr];
    }
    for (int half = 0; half < 2; half++){
        int o3 = half*128 + tid;
        float va[16];
        #pragma unroll
        for (int nr = 0; nr < 16; nr++) va[nr] = 0.f;
        for (int c = 0; c < 128; c++){
            float wv = v_w[c*256 + o3];
            #pragma unroll
            for (int nr = 0; nr < 16; nr++) va[nr] += xr[nr][c] * wv;
        }
        #pragma unroll
        for (int nr = 0; nr < 16; nr++) vs[nr][o3] = va[nr];
    }
    __syncthreads();
    for (int half = 0; half < 2; half++){
        int cc = half*128 + tid;
        float w9[9];
        #pragma unroll
        for (int j = 0; j < 9; j++) w9[j] = cpe_w[cc*9 + j];
        float cb = cpe_b[cc];
        #pragma unroll
        for (int nr = 0; nr < 16; nr++){
            int y = nr >> 2, x = nr & 3;
            float acc = cb;
            #pragma unroll
            for (int dy = -1; dy <= 1; dy++)
                #pragma unroll
                for (int dx = -1; dx <= 1; dx++){
                    int yy = y+dy, xx = x+dx;
                    if (yy >= 0 && yy < 4 && xx >= 0 && xx < 4)
                        acc += vs[yy*4+xx][cc] * w9[(dy+1)*3 + dx+1];
                }
            g_v[(b*16 + nr)*256 + cc] = vs[nr][cc] + acc;
        }
    }
}

// ---------------- K7: attention (fused, Nr=16), bf16 out ----------------
__global__ void k_attn(){
    __shared__ float ks[8][16][16];
    __shared__ float vs2[16][256];
    int b  = blockIdx.x >> 7;
    int tb = (blockIdx.x & 127) * 32;
    for (int i = threadIdx.x; i < 2048; i += 256){
        int m = i >> 7, j = i & 127;
        ks[j>>4][m][j&15] = g_k[(b*16 + m)*128 + j];
    }
    for (int i = threadIdx.x; i < 4096; i += 256){
        int m = i >> 8, cc2 = i & 255;
        vs2[m][cc2] = g_v[(b*16 + m)*256 + cc2];
    }
    __syncthreads();
    int h = threadIdx.x >> 5;
    int tk = threadIdx.x & 31;
    size_t n = (size_t)b*4096 + tb + tk;
    float qv[16];
    const float* qp = g_q + n*128 + h*16;
    #pragma unroll
    for (int d = 0; d < 16; d++) qv[d] = qp[d];
    float s[16];
    float mx = -1e30f;
    #pragma unroll
    for (int m = 0; m < 16; m++){
        float dot = 0.f;
        #pragma unroll
        for (int d = 0; d < 16; d++) dot += qv[d] * ks[h][m][d];
        s[m] = dot * 0.25f;
        mx = fmaxf(mx, s[m]);
    }
    float sum = 0.f;
    #pragma unroll
    for (int m = 0; m < 16; m++){ s[m] = expf(s[m] - mx); sum += s[m]; }
    float inv = 1.0f / sum;
    bf16* op = g_o + n*256 + h*32;
    #pragma unroll
    for (int d2 = 0; d2 < 32; d2++){
        float a = 0.f;
        #pragma unroll
        for (int m = 0; m < 16; m++) a += s[m] * vs2[m][h*32 + d2];
        op[d2] = __float2bfloat16(a * inv);
    }
}

// ---------------- gnorm: LN(512) over x2 half of g_h, token-layout bf16 out (coalesced) ----------------
__global__ void k_gnorm(const float* __restrict__ gw, const float* __restrict__ gb){
    int token = blockIdx.x*8 + (threadIdx.x >> 5);
    int lane = threadIdx.x & 31;
    const bf16* p = g_h + (size_t)token*1024 + 512;
    float s = 0.f, q = 0.f;
    float vals[16];
    #pragma unroll
    for (int j = 0; j < 16; j++){
        float v = __bfloat162float(p[lane + j*32]);
        vals[j] = v; s += v; q += v*v;
    }
    #pragma unroll
    for (int off = 16; off > 0; off >>= 1){
        s += __shfl_xor_sync(0xffffffff, s, off);
        q += __shfl_xor_sync(0xffffffff, q, off);
    }
    float m = s * (1.0f/512.0f);
    float var = q * (1.0f/512.0f) - m*m;
    float iv = rsqrtf(var + 1e-5f);
    bf16* o = g_x2t + (size_t)token*512;
    #pragma unroll
    for (int j = 0; j < 16; j++){
        int i = lane + j*32;
        o[i] = __float2bfloat16((vals[j] - m) * iv * gw[i] + gb[i]);
    }
}

// ---------------- transpose x2t (token) -> x2i (image), bf16 32x32 tiles ----------------
__global__ void k_trx2(){
    int b = blockIdx.z;
    int c0 = blockIdx.y * 32, n0 = blockIdx.x * 32;
    __shared__ bf16 tl[32][33];
    int tx = threadIdx.x, ty = threadIdx.y;
    for (int r = ty; r < 32; r += 8)
        tl[r][tx] = g_x2t[((size_t)(b*4096) + n0 + r)*512 + c0 + tx];
    __syncthreads();
    for (int r = ty; r < 32; r += 8)
        g_x2i[((size_t)(b*512 + c0 + r))*4096 + n0 + tx] = tl[tx][r];
}

// ---------------- depthwise 3x3 on 64x64, image layout, bf16 ----------------
__global__ void k_gconv(const float* __restrict__ gw, const float* __restrict__ gb){
    int bc = blockIdx.x;
    int c = bc & 511;
    const bf16* src = g_x2i + (size_t)bc*4096;
    bf16* dst = g_x2c + (size_t)bc*4096;
    __shared__ float tl[66][66];
    for (int i = threadIdx.x; i < 66*66; i += 256){
        int y = i / 66 - 1, x = i % 66 - 1;
        tl[y+1][x+1] = (y >= 0 && y < 64 && x >= 0 && x < 64) ? __bfloat162float(src[y*64 + x]) : 0.f;
    }
    __syncthreads();
    float w9[9];
    #pragma unroll
    for (int j = 0; j < 9; j++) w9[j] = gw[c*9 + j];
    float bias = gb[c];
    for (int i = threadIdx.x; i < 4096; i += 256){
        int y = i >> 6, x = i & 63;
        float a = bias;
        #pragma unroll
        for (int dy = 0; dy < 3; dy++)
            #pragma unroll
            for (int dx = 0; dx < 3; dx++)
                a += tl[y+dy][x+dx] * w9[dy*3 + dx];
        dst[i] = __float2bfloat16(a);
    }
}

// ---------------- transpose x2c back to tokens and gate with x1 -> g_gate bf16 ----------------
__global__ void k_gatemlp(){
    int b = blockIdx.z;
    int c0 = blockIdx.y * 32, n0 = blockIdx.x * 32;
    int tx = threadIdx.x, ty = threadIdx.y;
    __shared__ bf16 tl[32][33];
    for (int r = ty; r < 32; r += 8)
        tl[r][tx] = g_x2c[((size_t)(b*512 + c0 + r))*4096 + n0 + tx];
    __syncthreads();
    for (int r = ty; r < 32; r += 8){
        size_t tok = (size_t)b*4096 + n0 + r;
        float x1 = __bfloat162float(g_h[tok*1024 + c0 + tx]);
        float x2 = __bfloat162float(tl[tx][r]);
        g_gate[tok*512 + c0 + tx] = __float2bfloat16(x1 * x2);
    }
}

// ---------------- final: transpose fc2 token-layout temp -> [B,C,H,W] out ----------------
__global__ void k_out(const float* __restrict__ otmp, float* __restrict__ out){
    int b = blockIdx.z;
    int c0 = blockIdx.y * 32, n0 = blockIdx.x * 32;
    __shared__ float tl[32][33];
    int tx = threadIdx.x, ty = threadIdx.y;
    for (int r = ty; r < 32; r += 8)
        tl[r][tx] = otmp[((size_t)(b*4096) + n0 + r)*256 + c0 + tx];
    __syncthreads();
    for (int r = ty; r < 32; r += 8)
        out[((size_t)(b*256 + c0 + r))*4096 + n0 + tx] = tl[tx][r];
}

// ---------------- launcher ----------------
extern "C" void kernel_launch(void* const* d_in, const int* in_sizes, int n_in,
                              void* d_out, int out_size){
    const float* x        = (const float*)d_in[0];
    const float* sda_w    = (const float*)d_in[1];
    const float* sda_gnw  = (const float*)d_in[2];
    const float* sda_gnb  = (const float*)d_in[3];
    const float* n1w      = (const float*)d_in[4];
    const float* n1b      = (const float*)d_in[5];
    const float* red_w    = (const float*)d_in[6];
    const float* red_b    = (const float*)d_in[7];
    const float* dw_w     = (const float*)d_in[8];
    const float* dw_b     = (const float*)d_in[9];
    const float* conv_w   = (const float*)d_in[10];
    const float* conv_b   = (const float*)d_in[11];
    const float* na_w     = (const float*)d_in[12];
    const float* na_b     = (const float*)d_in[13];
    const float* q_w      = (const float*)d_in[14];
    const float* k_w      = (const float*)d_in[15];
    const float* v_w      = (const float*)d_in[16];
    const float* cpe_w    = (const float*)d_in[17];
    const float* cpe_b    = (const float*)d_in[18];
    const float* proj_w   = (const float*)d_in[19];
    const float* proj_b   = (const float*)d_in[20];
    const float* n2w      = (const float*)d_in[21];
    const float* n2b      = (const float*)d_in[22];
    const float* fc1_w    = (const float*)d_in[23];
    const float* fc1_b    = (const float*)d_in[24];
    const float* gn_w     = (const float*)d_in[25];
    const float* gn_b     = (const float*)d_in[26];
    const float* gc_w     = (const float*)d_in[27];
    const float* gc_b     = (const float*)d_in[28];
    const float* fc2_w    = (const float*)d_in[29];
    const float* fc2_b    = (const float*)d_in[30];
    float* out = (float*)d_out;

    float *p_res, *p_q;
    bf16 *p_tln, *p_o, *p_gate, *p_h;
    bf16 *p_qT, *p_projT, *p_fc1T, *p_fc2T;
    cudaGetSymbolAddress((void**)&p_res, g_res);
    cudaGetSymbolAddress((void**)&p_tln, g_tln);
    cudaGetSymbolAddress((void**)&p_q,   g_q);
    cudaGetSymbolAddress((void**)&p_o,   g_o);
    cudaGetSymbolAddress((void**)&p_gate,g_gate);
    cudaGetSymbolAddress((void**)&p_h,   g_h);
    cudaGetSymbolAddress((void**)&p_qT,  g_qT);
    cudaGetSymbolAddress((void**)&p_projT, g_projT);
    cudaGetSymbolAddress((void**)&p_fc1T, g_fc1T);
    cudaGetSymbolAddress((void**)&p_fc2T, g_fc2T);
    float* p_otmp = (float*)p_h;    // fc2 fp32 temp reuses g_h

    cudaFuncSetAttribute(k_gemm_bf<false,false,false>, cudaFuncAttributeMaxDynamicSharedMemorySize, GEMM_SMEM);
    cudaFuncSetAttribute(k_gemm_bf<false,true,false>,  cudaFuncAttributeMaxDynamicSharedMemorySize, GEMM_SMEM);
    cudaFuncSetAttribute(k_gemm_bf<true,false,true>,   cudaFuncAttributeMaxDynamicSharedMemorySize, GEMM_SMEM);

    // 0. weight transposes -> bf16 [N,K]
    k_tr<<<dim3(CRD/32, CC/32), dim3(32,8)>>>(q_w,    p_qT,   CC,   CRD);
    k_tr<<<dim3(CC/32,  CC/32), dim3(32,8)>>>(proj_w, p_projT, CC,  CC);
    k_tr<<<dim3(HID/32, CC/32), dim3(32,8)>>>(fc1_w,  p_fc1T, CC,   HID);
    k_tr<<<dim3(CC/32, HALF/32), dim3(32,8)>>>(fc2_w, p_fc2T, HALF, CC);

    // 1. means
    k_mean<<<BB*CC, 256>>>(x);
    // 2. SDAM conv1d + GN + relu
    k_sdam<<<BB*16*2, 256>>>(sda_w, sda_gnw, sda_gnb);
    // 3. gate + to tokens (fp32 residual)
    k_gate<<<dim3(2, 8, BB*HH), dim3(32, 8)>>>(x);
    // 4. LN1 -> bf16
    k_ln256<<<BN/8, 256>>>(p_res, p_tln, n1w, n1b, 1e-6f);
    // 5. reduction conv chain
    k_red<<<BB*CC, 256>>>(red_w, red_b, dw_w, dw_b);
    // 6. small per-batch stage
    k_small<<<BB, 128>>>(conv_w, conv_b, na_w, na_b, k_w, v_w, cpe_w, cpe_b);
    // 7. Q = tln @ q_w
    k_gemm_bf<false,false,false><<<dim3(CRD/128, BN/128), 256, GEMM_SMEM>>>(p_tln, p_qT, nullptr, nullptr, p_q, BN, CRD, CC);
    // 8. attention -> bf16
    k_attn<<<BN/32, 256>>>();
    // 9. proj + residual -> fp32 g_res
    k_gemm_bf<false,true,false><<<dim3(CC/128, BN/128), 256, GEMM_SMEM>>>(p_o, p_projT, proj_b, p_res, p_res, BN, CC, CC);
    // 10. LN2 -> bf16
    k_ln256<<<BN/8, 256>>>(p_res, p_tln, n2w, n2b, 1e-6f);
    // 11. fc1 + gelu -> bf16 g_h
    k_gemm_bf<true,false,true><<<dim3(HID/128, BN/128), 256, GEMM_SMEM>>>(p_tln, p_fc1T, fc1_b, nullptr, p_h, BN, HID, CC);
    // 12. gnorm -> token-layout bf16 (coalesced)
    k_gnorm<<<BN/8, 256>>>(gn_w, gn_b);
    // 13. transpose to image layout
    k_trx2<<<dim3(NN/32, HALF/32, BB), dim3(32, 8)>>>();
    // 14. depthwise 3x3
    k_gconv<<<BB*HALF, 256>>>(gc_w, gc_b);
    // 15. transpose back + gate with x1 -> bf16
    k_gatemlp<<<dim3(NN/32, HALF/32, BB), dim3(32, 8)>>>();
    // 16. fc2 + bias + residual -> fp32 token-layout temp
    k_gemm_bf<false,true,false><<<dim3(CC/128, BN/128), 256, GEMM_SMEM>>>(p_gate, p_fc2T, fc2_b, p_res, p_otmp, BN, CC, HALF);
    // 17. final transpose to [B,C,H,W]
    k_out<<<dim3(NN/32, CC/32, BB), dim3(32, 8)>>>(p_otmp, out);
}

// round 16
// speedup vs baseline: 1.5769x; 1.0258x over previous
#include <cuda_runtime.h>
#include <cuda_bf16.h>
#include <math.h>
#include <stdint.h>

// ---------------- constants ----------------
#define BB 16
#define CC 256
#define HH 64
#define WW 64
#define NN 4096            // tokens per batch
#define BN (BB*NN)         // 65536 total tokens
#define CRD 128
#define NHD 8
#define NRD 16             // reduced tokens (4x4)
#define HID 1024
#define HALF 512

typedef __nv_bfloat16 bf16;

// ---------------- scratch (device globals; no allocation) ----------------
__device__ float g_xh[BB*CC*HH];
__device__ float g_xw[BB*CC*WW];
__device__ float g_res[(size_t)BN*CC];      // gated tokens (fp32 residual)
__device__ bf16  g_tln[(size_t)BN*CC];      // LN1/LN2 out (bf16, GEMM A)
__device__ float g_q[(size_t)BN*CRD];
__device__ bf16  g_o[(size_t)BN*CC];        // attention out (bf16, GEMM A)
__device__ float g_red[BB*CC*NRD];
__device__ float g_k[BB*NRD*CRD];
__device__ float g_v[BB*NRD*CC];
__device__ bf16  g_h[(size_t)BN*HID];       // fc1 out (bf16); reused as fc2 fp32 temp
__device__ bf16  g_x2t[(size_t)BN*HALF];    // gnormed x2, token layout
__device__ bf16  g_x2i[(size_t)BN*HALF];    // image layout
__device__ bf16  g_x2c[(size_t)BN*HALF];    // after gconv, image layout
__device__ bf16  g_gate[(size_t)BN*HALF];   // x1*x2 token layout (GEMM A)
// transposed bf16 weights [N,K]
__device__ bf16 g_qT[CRD*CC];
__device__ bf16 g_projT[CC*CC];
__device__ bf16 g_fc1T[HID*CC];
__device__ bf16 g_fc2T[CC*HALF];

__device__ __forceinline__ float gelu_f(float v){
    return 0.5f * v * (1.0f + erff(v * 0.70710678118654752f));
}
__device__ __forceinline__ uint32_t smem_u32(const void* p){
    uint32_t a;
    asm("{ .reg .u64 t; cvta.to.shared.u64 t, %1; cvt.u32.u64 %0, t; }" : "=r"(a) : "l"(p));
    return a;
}
__device__ __forceinline__ void cp16(uint32_t dst, const void* src){
    asm volatile("cp.async.cg.shared.global [%0], [%1], 16;" :: "r"(dst), "l"(src));
}
#define CP_COMMIT() asm volatile("cp.async.commit_group;" ::: "memory")
#define CP_WAIT0()  asm volatile("cp.async.wait_group 0;" ::: "memory")
#define CP_WAIT1()  asm volatile("cp.async.wait_group 1;" ::: "memory")

__device__ __forceinline__ void mma_bf16(float* c, const uint32_t* a, const uint32_t* b){
    asm volatile(
        "mma.sync.aligned.m16n8k16.row.col.f32.bf16.bf16.f32 "
        "{%0,%1,%2,%3}, {%4,%5,%6,%7}, {%8,%9}, {%0,%1,%2,%3};"
        : "+f"(c[0]), "+f"(c[1]), "+f"(c[2]), "+f"(c[3])
        : "r"(a[0]), "r"(a[1]), "r"(a[2]), "r"(a[3]), "r"(b[0]), "r"(b[1]));
}
__device__ __forceinline__ void ldsm_x4(uint32_t& r0, uint32_t& r1, uint32_t& r2, uint32_t& r3, uint32_t addr){
    asm volatile("ldmatrix.sync.aligned.m8n8.x4.shared.b16 {%0,%1,%2,%3}, [%4];"
        : "=r"(r0), "=r"(r1), "=r"(r2), "=r"(r3) : "r"(addr));
}

// ---------------- weight transpose to bf16: WT[n*K+k] = bf16(W[k*N+n]) ----------------
__global__ void k_tr(const float* __restrict__ W, bf16* __restrict__ WT, int K, int Nn){
    __shared__ float t[32][33];
    int k0 = blockIdx.y*32, n0 = blockIdx.x*32;
    int tx = threadIdx.x, ty = threadIdx.y;
    for (int r = ty; r < 32; r += 8)
        t[r][tx] = W[(size_t)(k0+r)*Nn + n0 + tx];
    __syncthreads();
    for (int r = ty; r < 32; r += 8)
        WT[(size_t)(n0+r)*K + k0 + tx] = __float2bfloat16(t[tx][r]);
}

// ---------------- bf16 mma.sync GEMM: C[M,N] = A[M,K] * WT[N,K]^T ----------------
// CTA 128x128, warp tile 64x32, K chunk 32 bf16, 3-stage cp.async, ldmatrix, 2 CTAs/SM.
// pitch 40 bf16 (80B): conflict-free for both cp.async stores and ldmatrix phases.
#define PITCH 40
#define ABUF  5120                 // one 128x32 tile, bf16 units (128*40)
#define NSTG  3
#define GEMM_SMEM (NSTG*2*ABUF*2)  // 61440 bytes
template<bool GELU, bool RESID, bool OUTBF16>
__global__ __launch_bounds__(256, 2) void k_gemm_bf(
        const bf16* __restrict__ A, const bf16* __restrict__ WT,
        const float* __restrict__ bias, const float* __restrict__ resid,
        void* __restrict__ Cc, int M, int Nn, int K){
    extern __shared__ bf16 sm[];
    uint32_t sbase = smem_u32(sm);
    int tid = threadIdx.x, wid = tid >> 5, lane = tid & 31;
    int m0 = blockIdx.y * 128, n0 = blockIdx.x * 128;
    int wm = (wid & 1) * 64;
    int wn = (wid >> 1) * 32;

    float acc[4][4][4];
    #pragma unroll
    for (int i = 0; i < 4; i++)
        #pragma unroll
        for (int j = 0; j < 4; j++)
            #pragma unroll
            for (int q = 0; q < 4; q++) acc[i][j][q] = 0.f;

    int NC = K >> 5;
    int prow = tid >> 2, psg = tid & 3;   // cp.async: 64 rows/pass, 4x16B segs per 32-bf16 row
    // ldmatrix per-lane offsets (see fragment mapping in header comment)
    int a_row = wm + ((lane >> 3) & 1) * 8 + (lane & 7);
    int a_col = ((lane >> 4) & 1) * 8;
    int b_row = wn + ((lane >> 4) & 1) * 8 + (lane & 7);
    int b_col = ((lane >> 3) & 1) * 8;

    // prologue: prefetch stages 0,1
    #pragma unroll
    for (int s = 0; s < NSTG-1; s++){
        const bf16* Ag = A  + (size_t)m0*K + s*32;
        const bf16* Bg = WT + (size_t)n0*K + s*32;
        #pragma unroll
        for (int i = 0; i < 2; i++){
            int row = prow + i*64;
            cp16(sbase + (uint32_t)(s*ABUF + row*PITCH + psg*8)*2,          Ag + (size_t)row*K + psg*8);
            cp16(sbase + (uint32_t)((NSTG+s)*ABUF + row*PITCH + psg*8)*2,   Bg + (size_t)row*K + psg*8);
        }
        CP_COMMIT();
    }

    for (int ch = 0; ch < NC; ch++){
        if (ch == NC-1) CP_WAIT0(); else CP_WAIT1();
        __syncthreads();
        // prefetch chunk ch+2 into stage (ch+2)%3 (its last readers finished at the sync above)
        if (ch + 2 < NC){
            int s = (ch + 2) % NSTG;
            const bf16* Ag = A  + (size_t)m0*K + (ch+2)*32;
            const bf16* Bg = WT + (size_t)n0*K + (ch+2)*32;
            #pragma unroll
            for (int i = 0; i < 2; i++){
                int row = prow + i*64;
                cp16(sbase + (uint32_t)(s*ABUF + row*PITCH + psg*8)*2,        Ag + (size_t)row*K + psg*8);
                cp16(sbase + (uint32_t)((NSTG+s)*ABUF + row*PITCH + psg*8)*2, Bg + (size_t)row*K + psg*8);
            }
            CP_COMMIT();
        }
        int st = ch % NSTG;
        uint32_t as0 = sbase + (uint32_t)(st*ABUF)*2;
        uint32_t bs0 = sbase + (uint32_t)((NSTG + st)*ABUF)*2;
        #pragma unroll
        for (int kk = 0; kk < 2; kk++){
            uint32_t af[4][4];
            #pragma unroll
            for (int mi = 0; mi < 4; mi++)
                ldsm_x4(af[mi][0], af[mi][1], af[mi][2], af[mi][3],
                        as0 + (uint32_t)((a_row + mi*16)*PITCH + a_col + kk*16)*2);
            uint32_t bfr[4][2];
            #pragma unroll
            for (int p = 0; p < 2; p++)
                ldsm_x4(bfr[2*p][0], bfr[2*p][1], bfr[2*p+1][0], bfr[2*p+1][1],
                        bs0 + (uint32_t)((b_row + p*16)*PITCH + b_col + kk*16)*2);
            #pragma unroll
            for (int mi = 0; mi < 4; mi++)
                #pragma unroll
                for (int nj = 0; nj < 4; nj++)
                    mma_bf16(acc[mi][nj], af[mi], bfr[nj]);
        }
    }

    // epilogue
    int g = lane >> 2, cpair = (lane & 3) * 2;
    #pragma unroll
    for (int mi = 0; mi < 4; mi++){
        #pragma unroll
        for (int half = 0; half < 2; half++){
            int m = m0 + wm + mi*16 + g + half*8;
            #pragma unroll
            for (int nj = 0; nj < 4; nj++){
                int n = n0 + wn + nj*8 + cpair;
                float v0 = acc[mi][nj][half*2 + 0];
                float v1 = acc[mi][nj][half*2 + 1];
                if (bias){ v0 += bias[n]; v1 += bias[n+1]; }
                if (RESID){
                    const float* rp = resid + (size_t)m*Nn + n;
                    v0 += rp[0]; v1 += rp[1];
                }
                if (GELU){ v0 = gelu_f(v0); v1 = gelu_f(v1); }
                if (OUTBF16){
                    __nv_bfloat162 pk;
                    pk.x = __float2bfloat16(v0); pk.y = __float2bfloat16(v1);
                    *(__nv_bfloat162*)((bf16*)Cc + (size_t)m*Nn + n) = pk;
                } else {
                    *(float2*)((float*)Cc + (size_t)m*Nn + n) = make_float2(v0, v1);
                }
            }
        }
    }
}

// ---------------- K1: row/col means of x ----------------
__global__ void k_mean(const float* __restrict__ x){
    int bc = blockIdx.x;
    __shared__ float s[64][65];
    const float* p = x + (size_t)bc*4096;
    for (int i = threadIdx.x; i < 4096; i += 256) s[i>>6][i&63] = p[i];
    __syncthreads();
    int t = threadIdx.x;
    if (t < 64){
        float su = 0.f;
        #pragma unroll 8
        for (int w = 0; w < 64; w++) su += s[t][w];
        g_xh[bc*64 + t] = su * (1.0f/64.0f);
    } else if (t < 128){
        int w = t - 64;
        float su = 0.f;
        #pragma unroll 8
        for (int h = 0; h < 64; h++) su += s[h][w];
        g_xw[bc*64 + w] = su * (1.0f/64.0f);
    }
}

// ---------------- K2: dwconv1d(k=7,p=3) + GroupNorm(16) + ReLU ----------------
__global__ void k_sdam(const float* __restrict__ w7,
                       const float* __restrict__ gnw, const float* __restrict__ gnb){
    int id = blockIdx.x;
    int which = id & 1;
    int g = (id >> 1) & 15;
    int b = id >> 5;
    float* src = which ? g_xw : g_xh;
    __shared__ float si[16][64];
    __shared__ float so[16][64];
    __shared__ float r1[256], r2[256];
    int base = (b*256 + g*16) * 64;
    for (int i = threadIdx.x; i < 1024; i += 256) si[i>>6][i&63] = src[base + i];
    __syncthreads();
    float p1 = 0.f, p2 = 0.f;
    for (int i = threadIdx.x; i < 1024; i += 256){
        int c = i >> 6, l = i & 63;
        const float* wk = w7 + (g*16 + c)*7;
        float acc = 0.f;
        #pragma unroll
        for (int k = 0; k < 7; k++){
            int ll = l - 3 + k;
            if (ll >= 0 && ll < 64) acc += si[c][ll] * wk[k];
        }
        so[c][l] = acc;
        p1 += acc; p2 += acc*acc;
    }
    r1[threadIdx.x] = p1; r2[threadIdx.x] = p2;
    __syncthreads();
    for (int st = 128; st > 0; st >>= 1){
        if (threadIdx.x < st){ r1[threadIdx.x] += r1[threadIdx.x+st]; r2[threadIdx.x] += r2[threadIdx.x+st]; }
        __syncthreads();
    }
    float mean = r1[0] * (1.0f/1024.0f);
    float var  = r2[0] * (1.0f/1024.0f) - mean*mean;
    float iv = rsqrtf(var + 1e-5f);
    for (int i = threadIdx.x; i < 1024; i += 256){
        int c = i >> 6, l = i & 63;
        float v = (so[c][l] - mean) * iv * gnw[g*16 + c] + gnb[g*16 + c];
        src[base + i] = fmaxf(v, 0.f);
    }
}

// ---------------- K3: gate x by xh*xw and transpose to tokens (g_res fp32) ----------------
__global__ void k_gate(const float* __restrict__ x){
    int b = blockIdx.z >> 6, h = blockIdx.z & 63;
    int c0 = blockIdx.y * 32, w0 = blockIdx.x * 32;
    __shared__ float t2[32][33];
    int tx = threadIdx.x, ty = threadIdx.y;
    for (int r = ty; r < 32; r += 8){
        int c = c0 + r;
        int w = w0 + tx;
        t2[r][tx] = x[((size_t)(b*256 + c)*64 + h)*64 + w]
                  * g_xh[(b*256 + c)*64 + h] * g_xw[(b*256 + c)*64 + w];
    }
    __syncthreads();
    for (int r = ty; r < 32; r += 8){
        int w = w0 + r;
        g_res[((size_t)(b*4096) + h*64 + w)*256 + c0 + tx] = t2[tx][r];
    }
}

// ---------------- token LN over 256 (warp per token), bf16 out ----------------
__global__ void k_ln256(const float* __restrict__ in, bf16* __restrict__ out,
                        const float* __restrict__ w, const float* __restrict__ bb, float eps){
    int token = blockIdx.x*8 + (threadIdx.x >> 5);
    int lane = threadIdx.x & 31;
    const float* p = in + (size_t)token*256;
    float s = 0.f, q = 0.f;
    #pragma unroll
    for (int i = lane; i < 256; i += 32){ float v = p[i]; s += v; q += v*v; }
    #pragma unroll
    for (int off = 16; off > 0; off >>= 1){
        s += __shfl_xor_sync(0xffffffff, s, off);
        q += __shfl_xor_sync(0xffffffff, q, off);
    }
    float m = s * (1.0f/256.0f);
    float var = q * (1.0f/256.0f) - m*m;
    float iv = rsqrtf(var + eps);
    #pragma unroll
    for (int i = lane; i < 256; i += 32)
        out[(size_t)token*256 + i] = __float2bfloat16((p[i] - m) * iv * w[i] + bb[i]);
}

// ---------------- K5: reduction conv chain per (b,c): 64->16->4, then dw 3x3 ----------------
__global__ void k_red(const float* __restrict__ red_w, const float* __restrict__ red_b,
                      const float* __restrict__ dw_w, const float* __restrict__ dw_b){
    int bc = blockIdx.x;
    int b = bc >> 8, c = bc & 255;
    __shared__ float rw[16];
    __shared__ float dwv[9];
    __shared__ float o1[16][16];
    __shared__ float o2[4][4];
    int t = threadIdx.x;
    if (t < 16) rw[t] = red_w[c*16 + t];
    if (t >= 16 && t < 25) dwv[t-16] = dw_w[c*9 + (t-16)];
    __syncthreads();
    float rb = red_b[c];
    {
        int u = t >> 4, v = t & 15;
        float acc = 0.f;
        #pragma unroll
        for (int p = 0; p < 4; p++)
            #pragma unroll
            for (int q = 0; q < 4; q++)
                acc += __bfloat162float(g_tln[((size_t)(b*4096) + (4*u+p)*64 + (4*v+q))*256 + c]) * rw[p*4+q];
        o1[u][v] = acc + rb;
    }
    __syncthreads();
    if (t < 16){
        int y = t >> 2, x = t & 3;
        float acc = 0.f;
        #pragma unroll
        for (int p = 0; p < 4; p++)
            #pragma unroll
            for (int q = 0; q < 4; q++)
                acc += o1[4*y+p][4*x+q] * rw[p*4+q];
        o2[y][x] = acc + rb;
    }
    __syncthreads();
    if (t < 16){
        int y = t >> 2, x = t & 3;
        float acc = dw_b[c];
        #pragma unroll
        for (int dy = -1; dy <= 1; dy++)
            #pragma unroll
            for (int dx = -1; dx <= 1; dx++){
                int yy = y+dy, xx = x+dx;
                if (yy >= 0 && yy < 4 && xx >= 0 && xx < 4)
                    acc += o2[yy][xx] * dwv[(dy+1)*3 + dx+1];
            }
        g_red[(b*256 + c)*16 + t] = acc;
    }
}

// ---------------- K6: per batch — 1x1 conv + LN + gelu, k/v proj, CPE ----------------
__global__ void k_small(const float* __restrict__ conv_w, const float* __restrict__ conv_b,
                        const float* __restrict__ na_w, const float* __restrict__ na_b,
                        const float* __restrict__ k_w, const float* __restrict__ v_w,
                        const float* __restrict__ cpe_w, const float* __restrict__ cpe_b){
    int b = blockIdx.x;
    int tid = threadIdx.x;
    __shared__ float yr[256][16];
    __shared__ float xr[16][128];
    __shared__ float vs[16][256];
    __shared__ float mu2[16], iv2[16];
    for (int i = tid; i < 4096; i += 128) yr[i>>4][i&15] = g_red[b*4096 + i];
    __syncthreads();
    {
        float tmp[16];
        float cb = conv_b[tid];
        #pragma unroll
        for (int nr = 0; nr < 16; nr++) tmp[nr] = cb;
        for (int c = 0; c < 256; c++){
            float wv = conv_w[tid*256 + c];
            #pragma unroll
            for (int nr = 0; nr < 16; nr++) tmp[nr] += yr[c][nr] * wv;
        }
        #pragma unroll
        for (int nr = 0; nr < 16; nr++) xr[nr][tid] = tmp[nr];
    }
    __syncthreads();
    if (tid < 16){
        float s = 0.f, q = 0.f;
        for (int o = 0; o < 128; o++){ float v = xr[tid][o]; s += v; q += v*v; }
        float m = s * (1.0f/128.0f);
        float var = q * (1.0f/128.0f) - m*m;
        mu2[tid] = m; iv2[tid] = rsqrtf(var + 1e-5f);
    }
    __syncthreads();
    #pragma unroll
    for (int nr = 0; nr < 16; nr++){
        float v = (xr[nr][tid] - mu2[nr]) * iv2[nr] * na_w[tid] + na_b[tid];
        xr[nr][tid] = gelu_f(v);
    }
    __syncthreads();
    {
        float ka[16];
        #pragma unroll
        for (int nr = 0; nr < 16; nr++) ka[nr] = 0.f;
        for (int c = 0; c < 128; c++){
            float wv = k_w[c*128 + tid];
            #pragma unroll
            for (int nr = 0; nr < 16; nr++) ka[nr] += xr[nr][c] * wv;
        }
        #pragma unroll
        for (int nr = 0; nr < 16; nr++) g_k[(b*16 + nr)*128 + tid] = ka[nr];
    }
    for (int half = 0; half < 2; half++){
        int o3 = half*128 + tid;
        float va[16];
        #pragma unroll
        for (int nr = 0; nr < 16; nr++) va[nr] = 0.f;
        for (int c = 0; c < 128; c++){
            float wv = v_w[c*256 + o3];
            #pragma unroll
            for (int nr = 0; nr < 16; nr++) va[nr] += xr[nr][c] * wv;
        }
        #pragma unroll
        for (int nr = 0; nr < 16; nr++) vs[nr][o3] = va[nr];
    }
    __syncthreads();
    for (int half = 0; half < 2; half++){
        int cc = half*128 + tid;
        float w9[9];
        #pragma unroll
        for (int j = 0; j < 9; j++) w9[j] = cpe_w[cc*9 + j];
        float cb = cpe_b[cc];
        #pragma unroll
        for (int nr = 0; nr < 16; nr++){
            int y = nr >> 2, x = nr & 3;
            float acc = cb;
            #pragma unroll
            for (int dy = -1; dy <= 1; dy++)
                #pragma unroll
                for (int dx = -1; dx <= 1; dx++){
                    int yy = y+dy, xx = x+dx;
                    if (yy >= 0 && yy < 4 && xx >= 0 && xx < 4)
                        acc += vs[yy*4+xx][cc] * w9[(dy+1)*3 + dx+1];
                }
            g_v[(b*16 + nr)*256 + cc] = vs[nr][cc] + acc;
        }
    }
}

// ---------------- K7: attention (fused, Nr=16), bf16 out ----------------
__global__ void k_attn(){
    __shared__ float ks[8][16][16];
    __shared__ float vs2[16][256];
    int b  = blockIdx.x >> 7;
    int tb = (blockIdx.x & 127) * 32;
    for (int i = threadIdx.x; i < 2048; i += 256){
        int m = i >> 7, j = i & 127;
        ks[j>>4][m][j&15] = g_k[(b*16 + m)*128 + j];
    }
    for (int i = threadIdx.x; i < 4096; i += 256){
        int m = i >> 8, cc2 = i & 255;
        vs2[m][cc2] = g_v[(b*16 + m)*256 + cc2];
    }
    __syncthreads();
    int h = threadIdx.x >> 5;
    int tk = threadIdx.x & 31;
    size_t n = (size_t)b*4096 + tb + tk;
    float qv[16];
    const float* qp = g_q + n*128 + h*16;
    #pragma unroll
    for (int d = 0; d < 16; d++) qv[d] = qp[d];
    float s[16];
    float mx = -1e30f;
    #pragma unroll
    for (int m = 0; m < 16; m++){
        float dot = 0.f;
        #pragma unroll
        for (int d = 0; d < 16; d++) dot += qv[d] * ks[h][m][d];
        s[m] = dot * 0.25f;
        mx = fmaxf(mx, s[m]);
    }
    float sum = 0.f;
    #pragma unroll
    for (int m = 0; m < 16; m++){ s[m] = expf(s[m] - mx); sum += s[m]; }
    float inv = 1.0f / sum;
    bf16* op = g_o + n*256 + h*32;
    #pragma unroll
    for (int d2 = 0; d2 < 32; d2++){
        float a = 0.f;
        #pragma unroll
        for (int m = 0; m < 16; m++) a += s[m] * vs2[m][h*32 + d2];
        op[d2] = __float2bfloat16(a * inv);
    }
}

// ---------------- gnorm: LN(512) over x2 half of g_h, token-layout bf16 out (coalesced) ----------------
__global__ void k_gnorm(const float* __restrict__ gw, const float* __restrict__ gb){
    int token = blockIdx.x*8 + (threadIdx.x >> 5);
    int lane = threadIdx.x & 31;
    const bf16* p = g_h + (size_t)token*1024 + 512;
    float s = 0.f, q = 0.f;
    float vals[16];
    #pragma unroll
    for (int j = 0; j < 16; j++){
        float v = __bfloat162float(p[lane + j*32]);
        vals[j] = v; s += v; q += v*v;
    }
    #pragma unroll
    for (int off = 16; off > 0; off >>= 1){
        s += __shfl_xor_sync(0xffffffff, s, off);
        q += __shfl_xor_sync(0xffffffff, q, off);
    }
    float m = s * (1.0f/512.0f);
    float var = q * (1.0f/512.0f) - m*m;
    float iv = rsqrtf(var + 1e-5f);
    bf16* o = g_x2t + (size_t)token*512;
    #pragma unroll
    for (int j = 0; j < 16; j++){
        int i = lane + j*32;
        o[i] = __float2bfloat16((vals[j] - m) * iv * gw[i] + gb[i]);
    }
}

// ---------------- transpose x2t (token) -> x2i (image), bf16 32x32 tiles ----------------
__global__ void k_trx2(){
    int b = blockIdx.z;
    int c0 = blockIdx.y * 32, n0 = blockIdx.x * 32;
    __shared__ bf16 tl[32][33];
    int tx = threadIdx.x, ty = threadIdx.y;
    for (int r = ty; r < 32; r += 8)
        tl[r][tx] = g_x2t[((size_t)(b*4096) + n0 + r)*512 + c0 + tx];
    __syncthreads();
    for (int r = ty; r < 32; r += 8)
        g_x2i[((size_t)(b*512 + c0 + r))*4096 + n0 + tx] = tl[tx][r];
}

// ---------------- depthwise 3x3 on 64x64, image layout, bf16 ----------------
__global__ void k_gconv(const float* __restrict__ gw, const float* __restrict__ gb){
    int bc = blockIdx.x;
    int c = bc & 511;
    const bf16* src = g_x2i + (size_t)bc*4096;
    bf16* dst = g_x2c + (size_t)bc*4096;
    __shared__ float tl[66][66];
    for (int i = threadIdx.x; i < 66*66; i += 256){
        int y = i / 66 - 1, x = i % 66 - 1;
        tl[y+1][x+1] = (y >= 0 && y < 64 && x >= 0 && x < 64) ? __bfloat162float(src[y*64 + x]) : 0.f;
    }
    __syncthreads();
    float w9[9];
    #pragma unroll
    for (int j = 0; j < 9; j++) w9[j] = gw[c*9 + j];
    float bias = gb[c];
    for (int i = threadIdx.x; i < 4096; i += 256){
        int y = i >> 6, x = i & 63;
        float a = bias;
        #pragma unroll
        for (int dy = 0; dy < 3; dy++)
            #pragma unroll
            for (int dx = 0; dx < 3; dx++)
                a += tl[y+dy][x+dx] * w9[dy*3 + dx];
        dst[i] = __float2bfloat16(a);
    }
}

// ---------------- transpose x2c back to tokens and gate with x1 -> g_gate bf16 ----------------
__global__ void k_gatemlp(){
    int b = blockIdx.z;
    int c0 = blockIdx.y * 32, n0 = blockIdx.x * 32;
    int tx = threadIdx.x, ty = threadIdx.y;
    __shared__ bf16 tl[32][33];
    for (int r = ty; r < 32; r += 8)
        tl[r][tx] = g_x2c[((size_t)(b*512 + c0 + r))*4096 + n0 + tx];
    __syncthreads();
    for (int r = ty; r < 32; r += 8){
        size_t tok = (size_t)b*4096 + n0 + r;
        float x1 = __bfloat162float(g_h[tok*1024 + c0 + tx]);
        float x2 = __bfloat162float(tl[tx][r]);
        g_gate[tok*512 + c0 + tx] = __float2bfloat16(x1 * x2);
    }
}

// ---------------- final: transpose fc2 token-layout temp -> [B,C,H,W] out ----------------
__global__ void k_out(const float* __restrict__ otmp, float* __restrict__ out){
    int b = blockIdx.z;
    int c0 = blockIdx.y * 32, n0 = blockIdx.x * 32;
    __shared__ float tl[32][33];
    int tx = threadIdx.x, ty = threadIdx.y;
    for (int r = ty; r < 32; r += 8)
        tl[r][tx] = otmp[((size_t)(b*4096) + n0 + r)*256 + c0 + tx];
    __syncthreads();
    for (int r = ty; r < 32; r += 8)
        out[((size_t)(b*256 + c0 + r))*4096 + n0 + tx] = tl[tx][r];
}

// ---------------- launcher ----------------
extern "C" void kernel_launch(void* const* d_in, const int* in_sizes, int n_in,
                              void* d_out, int out_size){
    const float* x        = (const float*)d_in[0];
    const float* sda_w    = (const float*)d_in[1];
    const float* sda_gnw  = (const float*)d_in[2];
    const float* sda_gnb  = (const float*)d_in[3];
    const float* n1w      = (const float*)d_in[4];
    const float* n1b      = (const float*)d_in[5];
    const float* red_w    = (const float*)d_in[6];
    const float* red_b    = (const float*)d_in[7];
    const float* dw_w     = (const float*)d_in[8];
    const float* dw_b     = (const float*)d_in[9];
    const float* conv_w   = (const float*)d_in[10];
    const float* conv_b   = (const float*)d_in[11];
    const float* na_w     = (const float*)d_in[12];
    const float* na_b     = (const float*)d_in[13];
    const float* q_w      = (const float*)d_in[14];
    const float* k_w      = (const float*)d_in[15];
    const float* v_w      = (const float*)d_in[16];
    const float* cpe_w    = (const float*)d_in[17];
    const float* cpe_b    = (const float*)d_in[18];
    const float* proj_w   = (const float*)d_in[19];
    const float* proj_b   = (const float*)d_in[20];
    const float* n2w      = (const float*)d_in[21];
    const float* n2b      = (const float*)d_in[22];
    const float* fc1_w    = (const float*)d_in[23];
    const float* fc1_b    = (const float*)d_in[24];
    const float* gn_w     = (const float*)d_in[25];
    const float* gn_b     = (const float*)d_in[26];
    const float* gc_w     = (const float*)d_in[27];
    const float* gc_b     = (const float*)d_in[28];
    const float* fc2_w    = (const float*)d_in[29];
    const float* fc2_b    = (const float*)d_in[30];
    float* out = (float*)d_out;

    float *p_res, *p_q;
    bf16 *p_tln, *p_o, *p_gate, *p_h;
    bf16 *p_qT, *p_projT, *p_fc1T, *p_fc2T;
    cudaGetSymbolAddress((void**)&p_res, g_res);
    cudaGetSymbolAddress((void**)&p_tln, g_tln);
    cudaGetSymbolAddress((void**)&p_q,   g_q);
    cudaGetSymbolAddress((void**)&p_o,   g_o);
    cudaGetSymbolAddress((void**)&p_gate,g_gate);
    cudaGetSymbolAddress((void**)&p_h,   g_h);
    cudaGetSymbolAddress((void**)&p_qT,  g_qT);
    cudaGetSymbolAddress((void**)&p_projT, g_projT);
    cudaGetSymbolAddress((void**)&p_fc1T, g_fc1T);
    cudaGetSymbolAddress((void**)&p_fc2T, g_fc2T);
    float* p_otmp = (float*)p_h;    // fc2 fp32 temp reuses g_h

    cudaFuncSetAttribute(k_gemm_bf<false,false,false>, cudaFuncAttributeMaxDynamicSharedMemorySize, GEMM_SMEM);
    cudaFuncSetAttribute(k_gemm_bf<false,true,false>,  cudaFuncAttributeMaxDynamicSharedMemorySize, GEMM_SMEM);
    cudaFuncSetAttribute(k_gemm_bf<true,false,true>,   cudaFuncAttributeMaxDynamicSharedMemorySize, GEMM_SMEM);

    // 0. weight transposes -> bf16 [N,K]
    k_tr<<<dim3(CRD/32, CC/32), dim3(32,8)>>>(q_w,    p_qT,   CC,   CRD);
    k_tr<<<dim3(CC/32,  CC/32), dim3(32,8)>>>(proj_w, p_projT, CC,  CC);
    k_tr<<<dim3(HID/32, CC/32), dim3(32,8)>>>(fc1_w,  p_fc1T, CC,   HID);
    k_tr<<<dim3(CC/32, HALF/32), dim3(32,8)>>>(fc2_w, p_fc2T, HALF, CC);

    // 1. means
    k_mean<<<BB*CC, 256>>>(x);
    // 2. SDAM conv1d + GN + relu
    k_sdam<<<BB*16*2, 256>>>(sda_w, sda_gnw, sda_gnb);
    // 3. gate + to tokens (fp32 residual)
    k_gate<<<dim3(2, 8, BB*HH), dim3(32, 8)>>>(x);
    // 4. LN1 -> bf16
    k_ln256<<<BN/8, 256>>>(p_res, p_tln, n1w, n1b, 1e-6f);
    // 5. reduction conv chain
    k_red<<<BB*CC, 256>>>(red_w, red_b, dw_w, dw_b);
    // 6. small per-batch stage
    k_small<<<BB, 128>>>(conv_w, conv_b, na_w, na_b, k_w, v_w, cpe_w, cpe_b);
    // 7. Q = tln @ q_w
    k_gemm_bf<false,false,false><<<dim3(CRD/128, BN/128), 256, GEMM_SMEM>>>(p_tln, p_qT, nullptr, nullptr, p_q, BN, CRD, CC);
    // 8. attention -> bf16
    k_attn<<<BN/32, 256>>>();
    // 9. proj + residual -> fp32 g_res
    k_gemm_bf<false,true,false><<<dim3(CC/128, BN/128), 256, GEMM_SMEM>>>(p_o, p_projT, proj_b, p_res, p_res, BN, CC, CC);
    // 10. LN2 -> bf16
    k_ln256<<<BN/8, 256>>>(p_res, p_tln, n2w, n2b, 1e-6f);
    // 11. fc1 + gelu -> bf16 g_h
    k_gemm_bf<true,false,true><<<dim3(HID/128, BN/128), 256, GEMM_SMEM>>>(p_tln, p_fc1T, fc1_b, nullptr, p_h, BN, HID, CC);
    // 12. gnorm -> token-layout bf16 (coalesced)
    k_gnorm<<<BN/8, 256>>>(gn_w, gn_b);
    // 13. transpose to image layout
    k_trx2<<<dim3(NN/32, HALF/32, BB), dim3(32, 8)>>>();
    // 14. depthwise 3x3
    k_gconv<<<BB*HALF, 256>>>(gc_w, gc_b);
    // 15. transpose back + gate with x1 -> bf16
    k_gatemlp<<<dim3(NN/32, HALF/32, BB), dim3(32, 8)>>>();
    // 16. fc2 + bias + residual -> fp32 token-layout temp
    k_gemm_bf<false,true,false><<<dim3(CC/128, BN/128), 256, GEMM_SMEM>>>(p_gate, p_fc2T, fc2_b, p_res, p_otmp, BN, CC, HALF);
    // 17. final transpose to [B,C,H,W]
    k_out<<<dim3(NN/32, CC/32, BB), dim3(32, 8)>>>(p_otmp, out);
}